// round 13
// baseline (speedup 1.0000x reference)
#include <cuda_runtime.h>
#include <stdint.h>

// HDCTokenEncoder: out[b,i,d] = item_memory[tok[b,i]][(d - i) mod D] * 0.01f
// (L2 norm of every +/-1 row of length 10000 is exactly 100, exact in fp32,
//  so normalization == multiply by 0.01f, bit-identical to the reference.)
//
// R6: kill the second (B) global load. Consecutive lanes hold consecutive
// k (mod D4), so the straddle components come from lane+1 via shfl; only
// lane 31 does a tiny predicated load. Cuts L1 wavefronts/128B from ~3 to ~2.

#define HDC_D    10000
#define HDC_D4   2500      // D / 4
#define HDC_S    2048
#define NTHREADS 256
#define NITER    10        // ceil(HDC_D4 / NTHREADS)

__global__ void __launch_bounds__(NTHREADS)
hdc_encode_kernel(const int* __restrict__ tok,
                  const float4* __restrict__ item,   // [V][D4]
                  float4* __restrict__ out)          // [B*S][D4]
{
    const int row = blockIdx.x;          // 0 .. B*S-1
    const int i   = row & (HDC_S - 1);   // position within sequence
    const int t   = __ldg(tok + row);

    const int Dmi = HDC_D - i;           // rotation: out_flat[d] = row_flat[(d + Dmi) % D]
    int r4        = Dmi >> 2;            // rotation in float4 units (2500 when i == 0)
    const int a   = Dmi & 3;             // residual element shift 0..3
    if (r4 >= HDC_D4) r4 -= HDC_D4;

    const float4* __restrict__ src  = item + (size_t)t * HDC_D4;
    const float*  __restrict__ srcf = (const float*)src;
    float4* __restrict__       orow = out  + (size_t)row * HDC_D4;
    const float sc   = 0.01f;
    const int   lane = threadIdx.x & 31;

    // out4[q] = floats src_flat[4*(q + r4) + a .. +3] (mod D).
    // k == (q + r4) mod D4 maintained incrementally. Within a warp consecutive
    // lanes hold consecutive k (mod D4), so B (= src4[(k+1) mod D4]) is the
    // next lane's A — fetched with shfl.down; lane 31 loads it directly.
    int q = threadIdx.x;
    int k = q + r4; if (k >= HDC_D4) k -= HDC_D4;

    if (a == 0) {
        for (; q < HDC_D4; q += NTHREADS) {
            float4 A = __ldg(src + k);
            float4 v; v.x = A.x * sc; v.y = A.y * sc; v.z = A.z * sc; v.w = A.w * sc;
            __stcs(orow + q, v);
            k += NTHREADS; if (k >= HDC_D4) k -= HDC_D4;
        }
        return;
    }

    // a != 0 paths: fixed trip count, all lanes converged for the shuffles.
    // Loads always use wrapped k (in-bounds even when q >= D4); store predicated.
    if (a == 1) {
        #pragma unroll
        for (int it = 0; it < NITER; ++it) {
            float4 A  = __ldg(src + k);
            float  bx = __shfl_down_sync(0xffffffffu, A.x, 1);
            if (lane == 31) {
                int kn = k + 1; if (kn == HDC_D4) kn = 0;
                bx = __ldg(srcf + 4 * kn);
            }
            if (q < HDC_D4) {
                float4 v; v.x = A.y * sc; v.y = A.z * sc; v.z = A.w * sc; v.w = bx * sc;
                __stcs(orow + q, v);
            }
            q += NTHREADS;
            k += NTHREADS; if (k >= HDC_D4) k -= HDC_D4;
        }
    } else if (a == 2) {
        #pragma unroll
        for (int it = 0; it < NITER; ++it) {
            float4 A  = __ldg(src + k);
            float  bx = __shfl_down_sync(0xffffffffu, A.x, 1);
            float  by = __shfl_down_sync(0xffffffffu, A.y, 1);
            if (lane == 31) {
                int kn = k + 1; if (kn == HDC_D4) kn = 0;
                float2 Bv = __ldg((const float2*)(srcf + 4 * kn));  // 16B-aligned
                bx = Bv.x; by = Bv.y;
            }
            if (q < HDC_D4) {
                float4 v; v.x = A.z * sc; v.y = A.w * sc; v.z = bx * sc; v.w = by * sc;
                __stcs(orow + q, v);
            }
            q += NTHREADS;
            k += NTHREADS; if (k >= HDC_D4) k -= HDC_D4;
        }
    } else {  // a == 3
        #pragma unroll
        for (int it = 0; it < NITER; ++it) {
            float4 A  = __ldg(src + k);
            float  bx = __shfl_down_sync(0xffffffffu, A.x, 1);
            float  by = __shfl_down_sync(0xffffffffu, A.y, 1);
            float  bz = __shfl_down_sync(0xffffffffu, A.z, 1);
            if (lane == 31) {
                int kn = k + 1; if (kn == HDC_D4) kn = 0;
                float4 Bv = __ldg(src + kn);
                bx = Bv.x; by = Bv.y; bz = Bv.z;
            }
            if (q < HDC_D4) {
                float4 v; v.x = A.w * sc; v.y = bx * sc; v.z = by * sc; v.w = bz * sc;
                __stcs(orow + q, v);
            }
            q += NTHREADS;
            k += NTHREADS; if (k >= HDC_D4) k -= HDC_D4;
        }
    }
}

extern "C" void kernel_launch(void* const* d_in, const int* in_sizes, int n_in,
                              void* d_out, int out_size)
{
    // Inputs: token_ids (int32, B*S=16384), item_memory (f32, V*D).
    // Robust to ordering: tokens is the smaller buffer.
    const void* p0 = d_in[0];
    const void* p1 = d_in[1];
    const int*    tok;
    const float4* item;
    int n_rows;
    if (in_sizes[0] <= in_sizes[1]) {
        tok    = (const int*)p0;
        item   = (const float4*)p1;
        n_rows = in_sizes[0];
    } else {
        tok    = (const int*)p1;
        item   = (const float4*)p0;
        n_rows = in_sizes[1];
    }

    float4* out = (float4*)d_out;
    hdc_encode_kernel<<<n_rows, NTHREADS>>>(tok, item, out);
}

// round 15
// speedup vs baseline: 1.0066x; 1.0066x over previous
#include <cuda_runtime.h>
#include <stdint.h>

// HDCTokenEncoder: out[b,i,d] = item_memory[tok[b,i]][(d - i) mod D] * 0.01f
// (L2 norm of every +/-1 row of length 10000 is exactly 100, exact in fp32,
//  so normalization == multiply by 0.01f, bit-identical to the reference.)
//
// R14: revert to R4 dual-aligned-load structure (shuffle variant was neutral:
// kernel is DRAM-write bound at ~6.1 TB/s). 512-thread blocks (better tail:
// 2500 = 4*512 + 452), light software pipelining for MLP. Item table (10 MB)
// stays L2-resident; the only DRAM stream is the 655 MB output write.

#define HDC_D    10000
#define HDC_D4   2500      // D / 4
#define HDC_S    2048
#define NTHREADS 512

__global__ void __launch_bounds__(NTHREADS)
hdc_encode_kernel(const int* __restrict__ tok,
                  const float4* __restrict__ item,   // [V][D4]
                  float4* __restrict__ out)          // [B*S][D4]
{
    const int row = blockIdx.x;          // 0 .. B*S-1
    const int i   = row & (HDC_S - 1);   // position within sequence
    const int t   = __ldg(tok + row);

    const int Dmi = HDC_D - i;           // rotation: out_flat[d] = row_flat[(d + Dmi) % D]
    int r4        = Dmi >> 2;            // rotation in float4 units (2500 when i == 0)
    const int a   = Dmi & 3;             // residual element shift 0..3
    if (r4 >= HDC_D4) r4 -= HDC_D4;

    const float4* __restrict__ src  = item + (size_t)t * HDC_D4;
    float4* __restrict__       orow = out  + (size_t)row * HDC_D4;
    const float sc = 0.01f;

    // out4[q] = floats src_flat[4*(q + r4) + a .. +3]  (mod D)
    int q = threadIdx.x;
    int k = q + r4; if (k >= HDC_D4) k -= HDC_D4;

    if (a == 0) {
        // Pure float4 rotation: one aligned load per store.
        #pragma unroll 2
        for (; q < HDC_D4; q += NTHREADS) {
            float4 A = __ldg(src + k);
            float4 v; v.x = A.x * sc; v.y = A.y * sc; v.z = A.z * sc; v.w = A.w * sc;
            __stcs(orow + q, v);
            k += NTHREADS; if (k >= HDC_D4) k -= HDC_D4;
        }
        return;
    }

    // a != 0: two aligned loads straddle the rotated window. B is the next
    // lane's A -> L1 hit. Software-pipelined: prefetch next A/B before store.
    int kn = k + 1; if (kn == HDC_D4) kn = 0;
    float4 A = __ldg(src + k);
    float4 B = __ldg(src + kn);

    while (true) {
        int q_cur = q;
        q += NTHREADS;
        float4 Acur = A, Bcur = B;

        if (q < HDC_D4) {   // prefetch next iteration's inputs
            k += NTHREADS; if (k >= HDC_D4) k -= HDC_D4;
            kn = k + 1;     if (kn == HDC_D4) kn = 0;
            A = __ldg(src + k);
            B = __ldg(src + kn);
        }

        float4 v;
        if (a == 1)      { v.x = Acur.y * sc; v.y = Acur.z * sc; v.z = Acur.w * sc; v.w = Bcur.x * sc; }
        else if (a == 2) { v.x = Acur.z * sc; v.y = Acur.w * sc; v.z = Bcur.x * sc; v.w = Bcur.y * sc; }
        else             { v.x = Acur.w * sc; v.y = Bcur.x * sc; v.z = Bcur.y * sc; v.w = Bcur.z * sc; }
        __stcs(orow + q_cur, v);

        if (q >= HDC_D4) break;
    }
}

extern "C" void kernel_launch(void* const* d_in, const int* in_sizes, int n_in,
                              void* d_out, int out_size)
{
    // Inputs: token_ids (int32, B*S=16384), item_memory (f32, V*D).
    // Robust to ordering: tokens is the smaller buffer.
    const void* p0 = d_in[0];
    const void* p1 = d_in[1];
    const int*    tok;
    const float4* item;
    int n_rows;
    if (in_sizes[0] <= in_sizes[1]) {
        tok    = (const int*)p0;
        item   = (const float4*)p1;
        n_rows = in_sizes[0];
    } else {
        tok    = (const int*)p1;
        item   = (const float4*)p0;
        n_rows = in_sizes[1];
    }

    float4* out = (float4*)d_out;
    hdc_encode_kernel<<<n_rows, NTHREADS>>>(tok, item, out);
}